// round 12
// baseline (speedup 1.0000x reference)
#include <cuda_runtime.h>
#include <cstdint>

#define NN 100000
#define NE 625000
#define DD 128
#define NB 98   // ceil(NN/1024) — persistent CSR grid

// GEMM tiling (R8 geometry): block 256x128, 16 warps (4x4), warp tile 64x32
#define BM 256
#define BN 128
#define BK 32
#define NTHR 512
#define PITCH 36                                   // floats per row (+4 pad)
#define STAGE_FLOATS (BM * PITCH + BN * PITCH)     // 13824
#define SMEM_BYTES (3 * STAGE_FLOATS * 4)          // 3 stages = 165888 B

// ---------------- device scratch (static, allowed) ----------------
__device__ int   g_is64;
__device__ int   g_bar_arrive;
__device__ int   g_bar_gen;
__device__ int   g_deg[NN];
__device__ int   g_off[NN];
__device__ int   g_cur[NN];
__device__ int   g_bsum[NB];
__device__ int   g_csr[NE];
__device__ float g_h[(size_t)NN * DD];     // tf32-rounded hidden
__device__ float g_wl1[DD * DD];           // tf32-rounded weights
__device__ float g_wr1[DD * DD];
__device__ float g_wl2[DD * DD];
__device__ float g_wr2[DD * DD];

// ---------------- helpers ----------------
__device__ __forceinline__ uint32_t smem_u32(const void* p) {
    uint32_t a;
    asm("{ .reg .u64 t; cvta.to.shared.u64 t, %1; cvt.u32.u64 %0, t; }" : "=r"(a) : "l"(p));
    return a;
}
__device__ __forceinline__ void cp16(uint32_t dst, const void* src, int sz) {
    asm volatile("cp.async.cg.shared.global [%0], [%1], 16, %2;"
                 :: "r"(dst), "l"(src), "r"(sz) : "memory");
}
__device__ __forceinline__ void cp_commit() {
    asm volatile("cp.async.commit_group;" ::: "memory");
}
__device__ __forceinline__ void cp_wait1() {
    asm volatile("cp.async.wait_group 1;" ::: "memory");
}
__device__ __forceinline__ unsigned f2tf(float f) {
    unsigned u;
    asm("cvt.rna.tf32.f32 %0, %1;" : "=r"(u) : "f"(f));
    return u;
}
__device__ __forceinline__ float f2tf_f(float f) {
    return __uint_as_float(f2tf(f));
}

// ---------------- dtype detection + barrier reset ----------------
__global__ void k_detect(const int* __restrict__ w) {
    int lane = threadIdx.x;
    int nz = 0;
    if (w[2 * lane + 1] != 0) nz = 1;
    if (w[2 * (lane + 32) + 1] != 0) nz = 1;
    unsigned m = __ballot_sync(0xFFFFFFFF, nz);
    if (lane == 0) {
        g_is64 = (m == 0u) ? 1 : 0;
        g_bar_arrive = 0;
        g_bar_gen = 0;
    }
}

__device__ __forceinline__ int edge_at(const void* ei, int idx, int is64) {
    if (is64) return (int)((const long long*)ei)[idx];
    return ((const int*)ei)[idx];
}

// ---------------- software grid barrier ----------------
__device__ __forceinline__ void gridbar(int* gen) {
    __threadfence();
    __syncthreads();
    if (threadIdx.x == 0) {
        int my = *gen + 1;
        if (atomicAdd(&g_bar_arrive, 1) == NB - 1) {
            atomicExch(&g_bar_arrive, 0);
            __threadfence();
            atomicExch(&g_bar_gen, my);
        } else {
            while (atomicAdd(&g_bar_gen, 0) != my) { }
        }
        *gen = my;
    }
    __syncthreads();
}

// ---------------- fused CSR build + weight tf32 conversion ----------------
__global__ __launch_bounds__(1024)
void k_csr(const void* __restrict__ ei,
           const float* __restrict__ W1l, const float* __restrict__ W1r,
           const float* __restrict__ W2l, const float* __restrict__ W2r) {
    __shared__ int s[1024];
    const int tid = threadIdx.x;
    const int bid = blockIdx.x;
    const int gid = bid * 1024 + tid;
    const int is64 = g_is64;
    int gen = 0;

    if (gid < NN) { g_deg[gid] = 0; g_cur[gid] = 0; }
    if (gid < DD * DD) {
        g_wl1[gid] = f2tf_f(W1l[gid]);
        g_wr1[gid] = f2tf_f(W1r[gid]);
        g_wl2[gid] = f2tf_f(W2l[gid]);
        g_wr2[gid] = f2tf_f(W2r[gid]);
    }
    gridbar(&gen);

    for (int e = gid; e < NE; e += NB * 1024)
        atomicAdd(&g_deg[edge_at(ei, NE + e, is64)], 1);
    gridbar(&gen);

    {
        int v = (gid < NN) ? g_deg[gid] : 0;
        s[tid] = v;
        __syncthreads();
        for (int o = 1; o < 1024; o <<= 1) {
            int t = (tid >= o) ? s[tid - o] : 0;
            __syncthreads();
            s[tid] += t;
            __syncthreads();
        }
        if (gid < NN) g_off[gid] = s[tid] - v;
        if (tid == 1023) g_bsum[bid] = s[tid];
    }
    gridbar(&gen);

    if (bid == 0) {
        int v = (tid < NB) ? g_bsum[tid] : 0;
        if (tid < 128) s[tid] = v;
        __syncthreads();
        for (int o = 1; o < 128; o <<= 1) {
            int t = (tid >= o && tid < 128) ? s[tid - o] : 0;
            __syncthreads();
            if (tid < 128) s[tid] += t;
            __syncthreads();
        }
        if (tid < NB) g_bsum[tid] = s[tid] - v;
    }
    gridbar(&gen);

    if (gid < NN) g_off[gid] += g_bsum[bid];
    gridbar(&gen);

    for (int e = gid; e < NE; e += NB * 1024) {
        int d = edge_at(ei, NE + e, is64);
        int pos = g_off[d] + atomicAdd(&g_cur[d], 1);
        g_csr[pos] = edge_at(ei, e, is64);
    }
}

// ---------------- fused gather + tf32 mma.sync dual GEMM ----------------
// C[i][o] = sum_k mean_j(X[j][k]) * Wl[o][k] + sum_k X[i][k] * Wr[o][k] + b[o]
// Tiles 0-3: A = per-CTA in-place mean-gather of X chunk cols [t*32,t*32+32),
//            tf32-rounded at smem write (replaces standalone k_agg).
// Tiles 4-7: A = X rows direct (cp.async); cvt at fragment load when cvtA2=1.
// B: cp.async from Wl/Wr (pre-rounded tf32).
__global__ __launch_bounds__(NTHR, 1)
void k_gemm(const float* __restrict__ X,
            const float* __restrict__ Wl, const float* __restrict__ Wr,
            const float* __restrict__ bias, float* __restrict__ C,
            int n, int doRelu, int cvtA2, int roundOut)
{
    extern __shared__ float S[];
    const uint32_t sb = smem_u32(S);
    const int tid  = threadIdx.x;
    const int lane = tid & 31;
    const int wid  = tid >> 5;
    const int warpM = wid >> 2;            // 0..3  (64-row slices)
    const int warpN = wid & 3;             // 0..3  (32-col slices)
    const int rowBase = warpM * 64;
    const int colBase = warpN * 32;
    const int row0 = blockIdx.x * BM;
    const int qid = lane >> 2;             // 0..7
    const int rid = lane & 3;              // 0..3

    float c[4][4][4];
#pragma unroll
    for (int mi = 0; mi < 4; mi++)
#pragma unroll
        for (int ni = 0; ni < 4; ni++)
#pragma unroll
            for (int t = 0; t < 4; t++) c[mi][ni][t] = 0.f;

    // async loader: B always; A only for tiles 4-7 (direct X rows)
    auto load_async = [&](int t) {
        if (t < 8) {
            const float* Bsrc = (t < 4) ? Wl : Wr;
            const int kc = (t & 3) * BK;
            const uint32_t abase = sb + (uint32_t)(t % 3) * (STAGE_FLOATS * 4);
            const uint32_t bbase = abase + BM * PITCH * 4;
            if (t >= 4) {
#pragma unroll
                for (int i = 0; i < 4; i++) {
                    int ch = tid + i * NTHR;            // 0..2047
                    int row = ch >> 3, c4 = ch & 7;
                    int gr = row0 + row;
                    int ok = (gr < n);
                    const float* src = X + (size_t)(ok ? gr : 0) * DD + kc + c4 * 4;
                    cp16(abase + row * (PITCH * 4) + c4 * 16, src, ok ? 16 : 0);
                }
            }
#pragma unroll
            for (int i = 0; i < 2; i++) {
                int ch = tid + i * NTHR;                // 0..1023
                int nr = ch >> 3, c4 = ch & 7;
                cp16(bbase + nr * (PITCH * 4) + c4 * 16,
                     Bsrc + (size_t)nr * DD + kc + c4 * 4, 16);
            }
        }
        cp_commit();   // uniform group accounting
    };

    // synchronous mean-gather into slot t%3 A-region (tiles 0-3).
    // warp w -> rows [16w, 16w+16); lane -> 1 column of the 32-chunk.
    auto gather_tile = [&](int t) {
        const int kc = t * BK;
        float* Adst = S + (t % 3) * STAGE_FLOATS;
        const float* Xc = X + kc + lane;
        for (int i = 0; i < 16; i++) {
            int rr = wid * 16 + i;
            int node = row0 + rr;
            float acc = 0.f;
            if (node < n) {
                int beg = g_off[node];
                int d = g_deg[node];
                int j = 0;
                for (; j + 1 < d; j += 2) {
                    int s0 = __ldg(&g_csr[beg + j]);
                    int s1 = __ldg(&g_csr[beg + j + 1]);
                    float v0 = __ldg(&Xc[(size_t)s0 * DD]);
                    float v1 = __ldg(&Xc[(size_t)s1 * DD]);
                    acc += v0 + v1;
                }
                if (j < d) acc += __ldg(&Xc[(size_t)__ldg(&g_csr[beg + j]) * DD]);
                float inv = (d > 0) ? (1.0f / (float)d) : 0.0f;
                acc = f2tf_f(acc * inv);
            }
            Adst[rr * PITCH + lane] = acc;    // 32 consecutive floats: conflict-free
        }
    };

    load_async(0);
    load_async(1);
    gather_tile(0);

    for (int t = 0; t < 8; t++) {
        cp_wait1();          // tile t's async group complete (<=1 group pending)
        __syncthreads();     // publish gather(t) STS + async fills; slot reuse safe
        load_async(t + 2);   // slot (t+2)%3 held tile t-1: consumed before this barrier

        const float* As = S + (t % 3) * STAGE_FLOATS;
        const uint32_t* Au = (const uint32_t*)As;
        const uint32_t* Bu = Au + BM * PITCH;
        const bool ca = cvtA2 && (t >= 4);   // uniform: raw x fragments need rounding

#pragma unroll
        for (int kk = 0; kk < BK; kk += 8) {
            unsigned af[4][4];
            unsigned bf[4][2];
            if (ca) {
#pragma unroll
                for (int mi = 0; mi < 4; mi++) {
                    const int rr = rowBase + mi * 16 + qid;
                    const int kc2 = kk + rid;
                    af[mi][0] = f2tf(As[rr * PITCH + kc2]);
                    af[mi][1] = f2tf(As[(rr + 8) * PITCH + kc2]);
                    af[mi][2] = f2tf(As[rr * PITCH + kc2 + 4]);
                    af[mi][3] = f2tf(As[(rr + 8) * PITCH + kc2 + 4]);
                }
            } else {
#pragma unroll
                for (int mi = 0; mi < 4; mi++) {
                    const int rr = rowBase + mi * 16 + qid;
                    const int kc2 = kk + rid;
                    af[mi][0] = Au[rr * PITCH + kc2];
                    af[mi][1] = Au[(rr + 8) * PITCH + kc2];
                    af[mi][2] = Au[rr * PITCH + kc2 + 4];
                    af[mi][3] = Au[(rr + 8) * PITCH + kc2 + 4];
                }
            }
#pragma unroll
            for (int ni = 0; ni < 4; ni++) {
                const int col = colBase + ni * 8 + qid;
                bf[ni][0] = Bu[col * PITCH + kk + rid];
                bf[ni][1] = Bu[col * PITCH + kk + 4 + rid];
            }
#pragma unroll
            for (int ni = 0; ni < 4; ni++) {
#pragma unroll
                for (int mi = 0; mi < 4; mi++) {
                    asm volatile(
                        "mma.sync.aligned.m16n8k8.row.col.f32.tf32.tf32.f32 "
                        "{%0,%1,%2,%3}, {%4,%5,%6,%7}, {%8,%9}, {%0,%1,%2,%3};\n"
                        : "+f"(c[mi][ni][0]), "+f"(c[mi][ni][1]),
                          "+f"(c[mi][ni][2]), "+f"(c[mi][ni][3])
                        : "r"(af[mi][0]), "r"(af[mi][1]),
                          "r"(af[mi][2]), "r"(af[mi][3]),
                          "r"(bf[ni][0]), "r"(bf[ni][1]));
                }
            }
        }

        if (t + 1 < 4) gather_tile(t + 1);   // overlaps other warps' MMAs via arbiter
    }

    // epilogue
#pragma unroll
    for (int mi = 0; mi < 4; mi++) {
#pragma unroll
        for (int ni = 0; ni < 4; ni++) {
            const int col = colBase + ni * 8 + 2 * rid;
            const float bv0 = __ldg(&bias[col]);
            const float bv1 = __ldg(&bias[col + 1]);
            const int rr0 = row0 + rowBase + mi * 16 + qid;
            if (rr0 < n) {
                float v0 = c[mi][ni][0] + bv0;
                float v1 = c[mi][ni][1] + bv1;
                if (doRelu) { v0 = fmaxf(v0, 0.f); v1 = fmaxf(v1, 0.f); }
                if (roundOut) { v0 = f2tf_f(v0); v1 = f2tf_f(v1); }
                *(float2*)&C[(size_t)rr0 * DD + col] = make_float2(v0, v1);
            }
            const int rr1 = rr0 + 8;
            if (rr1 < n) {
                float v2 = c[mi][ni][2] + bv0;
                float v3 = c[mi][ni][3] + bv1;
                if (doRelu) { v2 = fmaxf(v2, 0.f); v3 = fmaxf(v3, 0.f); }
                if (roundOut) { v2 = f2tf_f(v2); v3 = f2tf_f(v3); }
                *(float2*)&C[(size_t)rr1 * DD + col] = make_float2(v2, v3);
            }
        }
    }
}

// ---------------- launch ----------------
extern "C" void kernel_launch(void* const* d_in, const int* in_sizes, int n_in,
                              void* d_out, int out_size) {
    const float* x   = (const float*)d_in[0];
    const void*  ei  = d_in[1];
    const float* W1l = (const float*)d_in[2];
    const float* b1  = (const float*)d_in[3];
    const float* W1r = (const float*)d_in[4];
    const float* W2l = (const float*)d_in[5];
    const float* b2  = (const float*)d_in[6];
    const float* W2r = (const float*)d_in[7];
    float* out = (float*)d_out;

    void* p;
    cudaGetSymbolAddress(&p, g_h);   float* h   = (float*)p;
    cudaGetSymbolAddress(&p, g_wl1); float* wl1 = (float*)p;
    cudaGetSymbolAddress(&p, g_wr1); float* wr1 = (float*)p;
    cudaGetSymbolAddress(&p, g_wl2); float* wl2 = (float*)p;
    cudaGetSymbolAddress(&p, g_wr2); float* wr2 = (float*)p;

    cudaFuncSetAttribute(k_gemm, cudaFuncAttributeMaxDynamicSharedMemorySize, SMEM_BYTES);

    const int ngb = (NN + BM - 1) / BM;

    k_detect<<<1, 32>>>((const int*)ei);                    // #0
    k_csr<<<NB, 1024>>>(ei, W1l, W1r, W2l, W2r);            // #1

    // Layer 1: fused gather(x)+GEMM -> h (tf32-rounded)    // #2
    k_gemm<<<ngb, NTHR, SMEM_BYTES>>>(x, wl1, wr1, b1, h, NN, 1, 1, 1);

    // Layer 2: fused gather(h)+GEMM -> out                 // #3 (ncu window)
    k_gemm<<<ngb, NTHR, SMEM_BYTES>>>(h, wl2, wr2, b2, out, NN, 0, 0, 0);
}

// round 13
// speedup vs baseline: 3.2125x; 3.2125x over previous
#include <cuda_runtime.h>
#include <cuda_fp16.h>
#include <cstdint>

#define NN 100000
#define NE 625000
#define DD 128
#define NB 98   // ceil(NN/1024) — persistent CSR grid

// GEMM tiling: block 256x128, 16 warps (4x4), warp tile 64x32, fp16 m16n8k16
#define BM 256
#define BN 128
#define BK 32
#define NTHR 512
#define PITCH 40                                   // halfs per row (32 data + 8 pad)
#define STAGE_HALFS ((BM + BN) * PITCH)            // 15360
#define SMEM_BYTES (3 * STAGE_HALFS * 2)           // 3 stages = 92160 B

// ---------------- device scratch (static, allowed) ----------------
__device__ int    g_is64;
__device__ int    g_bar_arrive;
__device__ int    g_bar_gen;
__device__ int    g_deg[NN];
__device__ int    g_off[NN];
__device__ int    g_cur[NN];
__device__ int    g_bsum[NB];
__device__ int    g_csr[NE];
__device__ __half g_xh[(size_t)NN * DD];    // fp16 copy of x
__device__ __half g_agg[(size_t)NN * DD];   // fp16 aggregate
__device__ __half g_h[(size_t)NN * DD];     // fp16 hidden
__device__ __half g_wl1[DD * DD];           // fp16 weights
__device__ __half g_wr1[DD * DD];
__device__ __half g_wl2[DD * DD];
__device__ __half g_wr2[DD * DD];

// ---------------- helpers ----------------
__device__ __forceinline__ uint32_t smem_u32(const void* p) {
    uint32_t a;
    asm("{ .reg .u64 t; cvta.to.shared.u64 t, %1; cvt.u32.u64 %0, t; }" : "=r"(a) : "l"(p));
    return a;
}
__device__ __forceinline__ void cp16(uint32_t dst, const void* src, int sz) {
    asm volatile("cp.async.cg.shared.global [%0], [%1], 16, %2;"
                 :: "r"(dst), "l"(src), "r"(sz) : "memory");
}
__device__ __forceinline__ void cp_commit() {
    asm volatile("cp.async.commit_group;" ::: "memory");
}
__device__ __forceinline__ void cp_wait1() {
    asm volatile("cp.async.wait_group 1;" ::: "memory");
}

// ---------------- dtype detection + barrier reset ----------------
__global__ void k_detect(const int* __restrict__ w) {
    int lane = threadIdx.x;
    int nz = 0;
    if (w[2 * lane + 1] != 0) nz = 1;
    if (w[2 * (lane + 32) + 1] != 0) nz = 1;
    unsigned m = __ballot_sync(0xFFFFFFFF, nz);
    if (lane == 0) {
        g_is64 = (m == 0u) ? 1 : 0;
        g_bar_arrive = 0;
        g_bar_gen = 0;
    }
}

__device__ __forceinline__ int edge_at(const void* ei, int idx, int is64) {
    if (is64) return (int)((const long long*)ei)[idx];
    return ((const int*)ei)[idx];
}

// ---------------- software grid barrier ----------------
__device__ __forceinline__ void gridbar(int* gen) {
    __threadfence();
    __syncthreads();
    if (threadIdx.x == 0) {
        int my = *gen + 1;
        if (atomicAdd(&g_bar_arrive, 1) == NB - 1) {
            atomicExch(&g_bar_arrive, 0);
            __threadfence();
            atomicExch(&g_bar_gen, my);
        } else {
            while (atomicAdd(&g_bar_gen, 0) != my) { }
        }
        *gen = my;
    }
    __syncthreads();
}

// ---------------- fused CSR build + fp16 conversion of x and weights ----------------
__global__ __launch_bounds__(1024)
void k_csr(const void* __restrict__ ei, const float* __restrict__ x,
           const float* __restrict__ W1l, const float* __restrict__ W1r,
           const float* __restrict__ W2l, const float* __restrict__ W2r) {
    __shared__ int s[1024];
    const int tid = threadIdx.x;
    const int bid = blockIdx.x;
    const int gid = bid * 1024 + tid;
    const int is64 = g_is64;
    int gen = 0;

    if (gid < NN) { g_deg[gid] = 0; g_cur[gid] = 0; }
    if (gid < DD * DD) {
        g_wl1[gid] = __float2half_rn(W1l[gid]);
        g_wr1[gid] = __float2half_rn(W1r[gid]);
        g_wl2[gid] = __float2half_rn(W2l[gid]);
        g_wr2[gid] = __float2half_rn(W2r[gid]);
    }
    {   // x -> fp16 (12.8M elems as float4)
        const float4* xv = (const float4*)x;
        __half2* xh = (__half2*)g_xh;
        for (int i = gid; i < NN * DD / 4; i += NB * 1024) {
            float4 v = xv[i];
            xh[2 * i]     = __floats2half2_rn(v.x, v.y);
            xh[2 * i + 1] = __floats2half2_rn(v.z, v.w);
        }
    }
    gridbar(&gen);

    for (int e = gid; e < NE; e += NB * 1024)
        atomicAdd(&g_deg[edge_at(ei, NE + e, is64)], 1);
    gridbar(&gen);

    {
        int v = (gid < NN) ? g_deg[gid] : 0;
        s[tid] = v;
        __syncthreads();
        for (int o = 1; o < 1024; o <<= 1) {
            int t = (tid >= o) ? s[tid - o] : 0;
            __syncthreads();
            s[tid] += t;
            __syncthreads();
        }
        if (gid < NN) g_off[gid] = s[tid] - v;
        if (tid == 1023) g_bsum[bid] = s[tid];
    }
    gridbar(&gen);

    if (bid == 0) {
        int v = (tid < NB) ? g_bsum[tid] : 0;
        if (tid < 128) s[tid] = v;
        __syncthreads();
        for (int o = 1; o < 128; o <<= 1) {
            int t = (tid >= o && tid < 128) ? s[tid - o] : 0;
            __syncthreads();
            if (tid < 128) s[tid] += t;
            __syncthreads();
        }
        if (tid < NB) g_bsum[tid] = s[tid] - v;
    }
    gridbar(&gen);

    if (gid < NN) g_off[gid] += g_bsum[bid];
    gridbar(&gen);

    for (int e = gid; e < NE; e += NB * 1024) {
        int d = edge_at(ei, NE + e, is64);
        int pos = g_off[d] + atomicAdd(&g_cur[d], 1);
        g_csr[pos] = edge_at(ei, e, is64);
    }
}

// ---------------- mean aggregation: one warp per node, fp16 in/out, fp32 accum ----------------
__global__ void k_agg(const __half* __restrict__ X, __half* __restrict__ out) {
    int warp = (blockIdx.x * blockDim.x + threadIdx.x) >> 5;
    if (warp >= NN) return;
    int lane = threadIdx.x & 31;
    int beg = g_off[warp];
    int d = g_deg[warp];
    const uint2* Xv = (const uint2*)X;   // 4 halfs per lane slot; 32 slots per row
    float4 acc = make_float4(0.f, 0.f, 0.f, 0.f);
    int j = 0;
    for (; j + 1 < d; j += 2) {
        int s0 = __ldg(&g_csr[beg + j]);
        int s1 = __ldg(&g_csr[beg + j + 1]);
        uint2 u0 = __ldg(&Xv[(size_t)s0 * 32 + lane]);
        uint2 u1 = __ldg(&Xv[(size_t)s1 * 32 + lane]);
        float2 a = __half22float2(*(__half2*)&u0.x);
        float2 b = __half22float2(*(__half2*)&u0.y);
        float2 e = __half22float2(*(__half2*)&u1.x);
        float2 f = __half22float2(*(__half2*)&u1.y);
        acc.x += a.x + e.x; acc.y += a.y + e.y;
        acc.z += b.x + f.x; acc.w += b.y + f.y;
    }
    if (j < d) {
        int s0 = __ldg(&g_csr[beg + j]);
        uint2 u0 = __ldg(&Xv[(size_t)s0 * 32 + lane]);
        float2 a = __half22float2(*(__half2*)&u0.x);
        float2 b = __half22float2(*(__half2*)&u0.y);
        acc.x += a.x; acc.y += a.y; acc.z += b.x; acc.w += b.y;
    }
    float inv = (d > 0) ? (1.0f / (float)d) : 0.0f;
    uint2 o;
    *(__half2*)&o.x = __floats2half2_rn(acc.x * inv, acc.y * inv);
    *(__half2*)&o.y = __floats2half2_rn(acc.z * inv, acc.w * inv);
    ((uint2*)out)[(size_t)warp * 32 + lane] = o;
}

// ---------------- fp16 mma.sync fused dual GEMM, cp.async 3-stage ----------------
// C[i][o] = sum_k A1[i][k]*Wl[o][k] + sum_k A2[i][k]*Wr[o][k] + b[o]  (opt ReLU)
// Block 256x128, 16 warps (4x4), warp tile 64x32 = 4x4 m16n8k16 frags, BK=32.
// All operands fp16 in global; fp32 accumulate; outHalf selects fp16/fp32 store.
__global__ __launch_bounds__(NTHR, 1)
void k_gemm(const __half* __restrict__ A1, const __half* __restrict__ A2,
            const __half* __restrict__ Wl, const __half* __restrict__ Wr,
            const float* __restrict__ bias, void* __restrict__ Cout,
            int n, int doRelu, int outHalf)
{
    extern __shared__ __half S[];
    const uint32_t sb = smem_u32(S);
    const int tid  = threadIdx.x;
    const int lane = tid & 31;
    const int wid  = tid >> 5;
    const int warpM = wid >> 2;            // 0..3  (64-row slices)
    const int warpN = wid & 3;             // 0..3  (32-col slices)
    const int rowBase = warpM * 64;
    const int colBase = warpN * 32;
    const int row0 = blockIdx.x * BM;
    const int qid = lane >> 2;             // 0..7
    const int rid = lane & 3;              // 0..3

    float c[4][4][4];
#pragma unroll
    for (int mi = 0; mi < 4; mi++)
#pragma unroll
        for (int ni = 0; ni < 4; ni++)
#pragma unroll
            for (int t = 0; t < 4; t++) c[mi][ni][t] = 0.f;

    // tile loader: tile t (0..7) -> slot t%3. Rows are 32 halfs = 64B = 4x cp16.
    auto load_tile = [&](int t) {
        if (t < 8) {
            const __half* Asrc = (t < 4) ? A1 : A2;
            const __half* Bsrc = (t < 4) ? Wl : Wr;
            const int kc = (t & 3) * BK;
            const uint32_t abase = sb + (uint32_t)(t % 3) * (STAGE_HALFS * 2);
            const uint32_t bbase = abase + BM * PITCH * 2;
#pragma unroll
            for (int i = 0; i < 2; i++) {
                int ch = tid + i * NTHR;                // 0..1023 (256 rows x 4)
                int row = ch >> 2, c4 = ch & 3;
                int gr = row0 + row;
                int ok = (gr < n);
                const __half* src = Asrc + (size_t)(ok ? gr : 0) * DD + kc + c4 * 8;
                cp16(abase + row * (PITCH * 2) + c4 * 16, src, ok ? 16 : 0);
            }
            {
                int ch = tid;                            // 0..511 (128 rows x 4)
                int nr = ch >> 2, c4 = ch & 3;
                cp16(bbase + nr * (PITCH * 2) + c4 * 16,
                     Bsrc + (size_t)nr * DD + kc + c4 * 8, 16);
            }
        }
        cp_commit();   // commit even when empty to keep group accounting uniform
    };

    load_tile(0);
    load_tile(1);

    for (int t = 0; t < 8; t++) {
        cp_wait1();          // tile t's group complete (1 group may stay in flight)
        __syncthreads();     // writes visible; prev compute on reused slot done
        load_tile(t + 2);    // slot (t+2)%3 was tile t-1: free now

        const __half* As = S + (t % 3) * STAGE_HALFS;
        const __half* Bs = As + BM * PITCH;

#pragma unroll
        for (int kk = 0; kk < BK; kk += 16) {
            unsigned af[4][4];
            unsigned bf[4][2];
#pragma unroll
            for (int mi = 0; mi < 4; mi++) {
                const int rr = rowBase + mi * 16 + qid;
                const int kc2 = kk + 2 * rid;
                af[mi][0] = *(const unsigned*)&As[rr * PITCH + kc2];
                af[mi][1] = *(const unsigned*)&As[(rr + 8) * PITCH + kc2];
                af[mi][2] = *(const unsigned*)&As[rr * PITCH + kc2 + 8];
                af[mi][3] = *(const unsigned*)&As[(rr + 8) * PITCH + kc2 + 8];
            }
#pragma unroll
            for (int ni = 0; ni < 4; ni++) {
                const int col = colBase + ni * 8 + qid;
                bf[ni][0] = *(const unsigned*)&Bs[col * PITCH + kk + 2 * rid];
                bf[ni][1] = *(const unsigned*)&Bs[col * PITCH + kk + 2 * rid + 8];
            }
#pragma unroll
            for (int ni = 0; ni < 4; ni++) {
#pragma unroll
                for (int mi = 0; mi < 4; mi++) {
                    asm volatile(
                        "mma.sync.aligned.m16n8k16.row.col.f32.f16.f16.f32 "
                        "{%0,%1,%2,%3}, {%4,%5,%6,%7}, {%8,%9}, {%0,%1,%2,%3};\n"
                        : "+f"(c[mi][ni][0]), "+f"(c[mi][ni][1]),
                          "+f"(c[mi][ni][2]), "+f"(c[mi][ni][3])
                        : "r"(af[mi][0]), "r"(af[mi][1]),
                          "r"(af[mi][2]), "r"(af[mi][3]),
                          "r"(bf[ni][0]), "r"(bf[ni][1]));
                }
            }
        }
    }

    // epilogue
    float* Cf = (float*)Cout;
    __half* Ch = (__half*)Cout;
#pragma unroll
    for (int mi = 0; mi < 4; mi++) {
#pragma unroll
        for (int ni = 0; ni < 4; ni++) {
            const int col = colBase + ni * 8 + 2 * rid;
            const float bv0 = __ldg(&bias[col]);
            const float bv1 = __ldg(&bias[col + 1]);
            const int rr0 = row0 + rowBase + mi * 16 + qid;
            if (rr0 < n) {
                float v0 = c[mi][ni][0] + bv0;
                float v1 = c[mi][ni][1] + bv1;
                if (doRelu) { v0 = fmaxf(v0, 0.f); v1 = fmaxf(v1, 0.f); }
                if (outHalf) {
                    *(__half2*)&Ch[(size_t)rr0 * DD + col] = __floats2half2_rn(v0, v1);
                } else {
                    *(float2*)&Cf[(size_t)rr0 * DD + col] = make_float2(v0, v1);
                }
            }
            const int rr1 = rr0 + 8;
            if (rr1 < n) {
                float v2 = c[mi][ni][2] + bv0;
                float v3 = c[mi][ni][3] + bv1;
                if (doRelu) { v2 = fmaxf(v2, 0.f); v3 = fmaxf(v3, 0.f); }
                if (outHalf) {
                    *(__half2*)&Ch[(size_t)rr1 * DD + col] = __floats2half2_rn(v2, v3);
                } else {
                    *(float2*)&Cf[(size_t)rr1 * DD + col] = make_float2(v2, v3);
                }
            }
        }
    }
}

// ---------------- launch ----------------
extern "C" void kernel_launch(void* const* d_in, const int* in_sizes, int n_in,
                              void* d_out, int out_size) {
    const float* x   = (const float*)d_in[0];
    const void*  ei  = d_in[1];
    const float* W1l = (const float*)d_in[2];
    const float* b1  = (const float*)d_in[3];
    const float* W1r = (const float*)d_in[4];
    const float* W2l = (const float*)d_in[5];
    const float* b2  = (const float*)d_in[6];
    const float* W2r = (const float*)d_in[7];
    float* out = (float*)d_out;

    void* p;
    cudaGetSymbolAddress(&p, g_xh);  __half* xh  = (__half*)p;
    cudaGetSymbolAddress(&p, g_agg); __half* agg = (__half*)p;
    cudaGetSymbolAddress(&p, g_h);   __half* h   = (__half*)p;
    cudaGetSymbolAddress(&p, g_wl1); __half* wl1 = (__half*)p;
    cudaGetSymbolAddress(&p, g_wr1); __half* wr1 = (__half*)p;
    cudaGetSymbolAddress(&p, g_wl2); __half* wl2 = (__half*)p;
    cudaGetSymbolAddress(&p, g_wr2); __half* wr2 = (__half*)p;

    cudaFuncSetAttribute(k_gemm, cudaFuncAttributeMaxDynamicSharedMemorySize, SMEM_BYTES);

    const int ngb = (NN + BM - 1) / BM;

    k_detect<<<1, 32>>>((const int*)ei);                        // #0
    k_csr<<<NB, 1024>>>(ei, x, W1l, W1r, W2l, W2r);             // #1

    // Layer 1                                                   // #2, #3
    k_agg<<<(NN + 7) / 8, 256>>>(xh, agg);
    k_gemm<<<ngb, NTHR, SMEM_BYTES>>>(agg, xh, wl1, wr1, b1, h, NN, 1, 1);

    // Layer 2                                                   // #4, #5
    k_agg<<<(NN + 7) / 8, 256>>>(h, agg);
    k_gemm<<<ngb, NTHR, SMEM_BYTES>>>(agg, h, wl2, wr2, b2, out, NN, 0, 0);
}

// round 14
// speedup vs baseline: 3.6041x; 1.1219x over previous
#include <cuda_runtime.h>
#include <cuda_fp16.h>
#include <cstdint>

#define NN 100000
#define NE 625000
#define DD 128
#define NB 98   // ceil(NN/1024) — persistent CSR grid

// GEMM tiling: block 256x128, 16 warps (4x4), warp tile 64x32, fp16 m16n8k16
#define BM 256
#define BN 128
#define BK 32
#define NTHR 512
#define PITCH 40                                   // halfs per row (32 data + 8 pad)
#define STAGE_HALFS ((BM + BN) * PITCH)            // 15360
#define SMEM_BYTES (3 * STAGE_HALFS * 2)           // 3 stages = 92160 B

// ---------------- device scratch (static, allowed) ----------------
__device__ int    g_is64;
__device__ int    g_bar_arrive;
__device__ int    g_bar_gen;
__device__ int    g_deg[NN];
__device__ int    g_off[NN];
__device__ int    g_cur[NN];
__device__ int    g_bsum[NB];
__device__ int    g_csr[NE];
__device__ __half g_xh[(size_t)NN * DD];    // fp16 copy of x
__device__ __half g_agg[(size_t)NN * DD];   // fp16 aggregate
__device__ __half g_h[(size_t)NN * DD];     // fp16 hidden
__device__ __half g_wl1[DD * DD];           // fp16 weights
__device__ __half g_wr1[DD * DD];
__device__ __half g_wl2[DD * DD];
__device__ __half g_wr2[DD * DD];

// ---------------- helpers ----------------
__device__ __forceinline__ uint32_t smem_u32(const void* p) {
    uint32_t a;
    asm("{ .reg .u64 t; cvta.to.shared.u64 t, %1; cvt.u32.u64 %0, t; }" : "=r"(a) : "l"(p));
    return a;
}
__device__ __forceinline__ void cp16(uint32_t dst, const void* src, int sz) {
    asm volatile("cp.async.cg.shared.global [%0], [%1], 16, %2;"
                 :: "r"(dst), "l"(src), "r"(sz) : "memory");
}
__device__ __forceinline__ void cp_commit() {
    asm volatile("cp.async.commit_group;" ::: "memory");
}
__device__ __forceinline__ void cp_wait1() {
    asm volatile("cp.async.wait_group 1;" ::: "memory");
}
__device__ __forceinline__ void ldsm4(unsigned& r0, unsigned& r1, unsigned& r2,
                                      unsigned& r3, uint32_t addr) {
    asm volatile("ldmatrix.sync.aligned.m8n8.x4.shared.b16 {%0,%1,%2,%3}, [%4];"
                 : "=r"(r0), "=r"(r1), "=r"(r2), "=r"(r3) : "r"(addr));
}

// ---------------- dtype detection + barrier reset ----------------
__global__ void k_detect(const int* __restrict__ w) {
    int lane = threadIdx.x;
    int nz = 0;
    if (w[2 * lane + 1] != 0) nz = 1;
    if (w[2 * (lane + 32) + 1] != 0) nz = 1;
    unsigned m = __ballot_sync(0xFFFFFFFF, nz);
    if (lane == 0) {
        g_is64 = (m == 0u) ? 1 : 0;
        g_bar_arrive = 0;
        g_bar_gen = 0;
    }
}

__device__ __forceinline__ int edge_at(const void* ei, int idx, int is64) {
    if (is64) return (int)((const long long*)ei)[idx];
    return ((const int*)ei)[idx];
}

// ---------------- software grid barrier ----------------
__device__ __forceinline__ void gridbar(int* gen) {
    __threadfence();
    __syncthreads();
    if (threadIdx.x == 0) {
        int my = *gen + 1;
        if (atomicAdd(&g_bar_arrive, 1) == NB - 1) {
            atomicExch(&g_bar_arrive, 0);
            __threadfence();
            atomicExch(&g_bar_gen, my);
        } else {
            while (atomicAdd(&g_bar_gen, 0) != my) { }
        }
        *gen = my;
    }
    __syncthreads();
}

// ---------------- fused CSR build + fp16 conversion of x and weights ----------------
__global__ __launch_bounds__(1024)
void k_csr(const void* __restrict__ ei, const float* __restrict__ x,
           const float* __restrict__ W1l, const float* __restrict__ W1r,
           const float* __restrict__ W2l, const float* __restrict__ W2r) {
    __shared__ int s[1024];
    const int tid = threadIdx.x;
    const int bid = blockIdx.x;
    const int gid = bid * 1024 + tid;
    const int is64 = g_is64;
    int gen = 0;

    if (gid < NN) { g_deg[gid] = 0; g_cur[gid] = 0; }
    if (gid < DD * DD) {
        g_wl1[gid] = __float2half_rn(W1l[gid]);
        g_wr1[gid] = __float2half_rn(W1r[gid]);
        g_wl2[gid] = __float2half_rn(W2l[gid]);
        g_wr2[gid] = __float2half_rn(W2r[gid]);
    }
    {   // x -> fp16 (12.8M elems as float4)
        const float4* xv = (const float4*)x;
        __half2* xh = (__half2*)g_xh;
        for (int i = gid; i < NN * DD / 4; i += NB * 1024) {
            float4 v = xv[i];
            xh[2 * i]     = __floats2half2_rn(v.x, v.y);
            xh[2 * i + 1] = __floats2half2_rn(v.z, v.w);
        }
    }
    gridbar(&gen);

    for (int e = gid; e < NE; e += NB * 1024)
        atomicAdd(&g_deg[edge_at(ei, NE + e, is64)], 1);
    gridbar(&gen);

    {
        int v = (gid < NN) ? g_deg[gid] : 0;
        s[tid] = v;
        __syncthreads();
        for (int o = 1; o < 1024; o <<= 1) {
            int t = (tid >= o) ? s[tid - o] : 0;
            __syncthreads();
            s[tid] += t;
            __syncthreads();
        }
        if (gid < NN) g_off[gid] = s[tid] - v;
        if (tid == 1023) g_bsum[bid] = s[tid];
    }
    gridbar(&gen);

    if (bid == 0) {
        int v = (tid < NB) ? g_bsum[tid] : 0;
        if (tid < 128) s[tid] = v;
        __syncthreads();
        for (int o = 1; o < 128; o <<= 1) {
            int t = (tid >= o && tid < 128) ? s[tid - o] : 0;
            __syncthreads();
            if (tid < 128) s[tid] += t;
            __syncthreads();
        }
        if (tid < NB) g_bsum[tid] = s[tid] - v;
    }
    gridbar(&gen);

    if (gid < NN) g_off[gid] += g_bsum[bid];
    gridbar(&gen);

    for (int e = gid; e < NE; e += NB * 1024) {
        int d = edge_at(ei, NE + e, is64);
        int pos = g_off[d] + atomicAdd(&g_cur[d], 1);
        g_csr[pos] = edge_at(ei, e, is64);
    }
}

// ---------------- mean aggregation: one warp per node, fp16 in/out, fp32 accum ----------------
__global__ void k_agg(const __half* __restrict__ X, __half* __restrict__ out) {
    int warp = (blockIdx.x * blockDim.x + threadIdx.x) >> 5;
    if (warp >= NN) return;
    int lane = threadIdx.x & 31;
    int beg = g_off[warp];
    int d = g_deg[warp];
    const uint2* Xv = (const uint2*)X;   // 4 halfs per lane slot; 32 slots per row
    float4 acc = make_float4(0.f, 0.f, 0.f, 0.f);
    int j = 0;
    for (; j + 1 < d; j += 2) {
        int s0 = __ldg(&g_csr[beg + j]);
        int s1 = __ldg(&g_csr[beg + j + 1]);
        uint2 u0 = __ldg(&Xv[(size_t)s0 * 32 + lane]);
        uint2 u1 = __ldg(&Xv[(size_t)s1 * 32 + lane]);
        float2 a = __half22float2(*(__half2*)&u0.x);
        float2 b = __half22float2(*(__half2*)&u0.y);
        float2 e = __half22float2(*(__half2*)&u1.x);
        float2 f = __half22float2(*(__half2*)&u1.y);
        acc.x += a.x + e.x; acc.y += a.y + e.y;
        acc.z += b.x + f.x; acc.w += b.y + f.y;
    }
    if (j < d) {
        int s0 = __ldg(&g_csr[beg + j]);
        uint2 u0 = __ldg(&Xv[(size_t)s0 * 32 + lane]);
        float2 a = __half22float2(*(__half2*)&u0.x);
        float2 b = __half22float2(*(__half2*)&u0.y);
        acc.x += a.x; acc.y += a.y; acc.z += b.x; acc.w += b.y;
    }
    float inv = (d > 0) ? (1.0f / (float)d) : 0.0f;
    uint2 o;
    *(__half2*)&o.x = __floats2half2_rn(acc.x * inv, acc.y * inv);
    *(__half2*)&o.y = __floats2half2_rn(acc.z * inv, acc.w * inv);
    ((uint2*)out)[(size_t)warp * 32 + lane] = o;
}

// ---------------- fp16 mma.sync fused dual GEMM, ldmatrix feeds, cp.async 3-stage ----------------
// C[i][o] = sum_k A1[i][k]*Wl[o][k] + sum_k A2[i][k]*Wr[o][k] + b[o]  (opt ReLU)
// Block 256x128, 16 warps (4x4), warp tile 64x32 = 4x4 m16n8k16 frags, BK=32.
// Fragment feeds via ldmatrix.x4 (6 LDSM vs 24 LDS per kk-step).
__global__ __launch_bounds__(NTHR, 1)
void k_gemm(const __half* __restrict__ A1, const __half* __restrict__ A2,
            const __half* __restrict__ Wl, const __half* __restrict__ Wr,
            const float* __restrict__ bias, void* __restrict__ Cout,
            int n, int doRelu, int outHalf)
{
    extern __shared__ __half S[];
    const uint32_t sb = smem_u32(S);
    const int tid  = threadIdx.x;
    const int lane = tid & 31;
    const int wid  = tid >> 5;
    const int warpM = wid >> 2;            // 0..3  (64-row slices)
    const int warpN = wid & 3;             // 0..3  (32-col slices)
    const int rowBase = warpM * 64;
    const int colBase = warpN * 32;
    const int row0 = blockIdx.x * BM;
    const int qid = lane >> 2;             // 0..7
    const int rid = lane & 3;              // 0..3

    // ldmatrix lane-address components (halfs):
    // A x4 covers m16k16 of one mi: lanes 0-7 rows lo/k lo, 8-15 rows hi/k lo,
    //                               16-23 rows lo/k hi, 24-31 rows hi/k hi.
    const int a_lrow = rowBase + (lane & 7) + ((lane >> 3) & 1) * 8;
    const int a_lcol = (lane >> 4) * 8;
    // B x4 covers two ni blocks: lanes 0-7 ni0/k lo, 8-15 ni0/k hi,
    //                            16-23 ni1/k lo, 24-31 ni1/k hi.
    const int b_lrow = colBase + (lane & 7) + (lane >> 4) * 8;
    const int b_lcol = ((lane >> 3) & 1) * 8;

    float c[4][4][4];
#pragma unroll
    for (int mi = 0; mi < 4; mi++)
#pragma unroll
        for (int ni = 0; ni < 4; ni++)
#pragma unroll
            for (int t = 0; t < 4; t++) c[mi][ni][t] = 0.f;

    // tile loader: tile t (0..7) -> slot t%3. Rows are 32 halfs = 64B = 4x cp16.
    auto load_tile = [&](int t) {
        if (t < 8) {
            const __half* Asrc = (t < 4) ? A1 : A2;
            const __half* Bsrc = (t < 4) ? Wl : Wr;
            const int kc = (t & 3) * BK;
            const uint32_t abase = sb + (uint32_t)(t % 3) * (STAGE_HALFS * 2);
            const uint32_t bbase = abase + BM * PITCH * 2;
#pragma unroll
            for (int i = 0; i < 2; i++) {
                int ch = tid + i * NTHR;                // 0..1023 (256 rows x 4)
                int row = ch >> 2, c4 = ch & 3;
                int gr = row0 + row;
                int ok = (gr < n);
                const __half* src = Asrc + (size_t)(ok ? gr : 0) * DD + kc + c4 * 8;
                cp16(abase + row * (PITCH * 2) + c4 * 16, src, ok ? 16 : 0);
            }
            {
                int ch = tid;                            // 0..511 (128 rows x 4)
                int nr = ch >> 2, c4 = ch & 3;
                cp16(bbase + nr * (PITCH * 2) + c4 * 16,
                     Bsrc + (size_t)nr * DD + kc + c4 * 8, 16);
            }
        }
        cp_commit();   // commit even when empty to keep group accounting uniform
    };

    load_tile(0);
    load_tile(1);

    for (int t = 0; t < 8; t++) {
        cp_wait1();          // tile t's group complete (1 group may stay in flight)
        __syncthreads();     // writes visible; prev compute on reused slot done
        load_tile(t + 2);    // slot (t+2)%3 was tile t-1: free now

        const uint32_t slotBase = sb + (uint32_t)(t % 3) * (STAGE_HALFS * 2);
        const uint32_t aAddr = slotBase + (uint32_t)(a_lrow * PITCH + a_lcol) * 2;
        const uint32_t bAddr = slotBase + (uint32_t)(BM * PITCH) * 2
                             + (uint32_t)(b_lrow * PITCH + b_lcol) * 2;

#pragma unroll
        for (int kk = 0; kk < BK; kk += 16) {
            unsigned af[4][4];
            unsigned bf[4][2];
#pragma unroll
            for (int mi = 0; mi < 4; mi++)
                ldsm4(af[mi][0], af[mi][1], af[mi][2], af[mi][3],
                      aAddr + (uint32_t)(mi * 16 * PITCH + kk) * 2);
#pragma unroll
            for (int np = 0; np < 2; np++)
                ldsm4(bf[2 * np][0], bf[2 * np][1], bf[2 * np + 1][0], bf[2 * np + 1][1],
                      bAddr + (uint32_t)(np * 16 * PITCH + kk) * 2);
#pragma unroll
            for (int ni = 0; ni < 4; ni++) {
#pragma unroll
                for (int mi = 0; mi < 4; mi++) {
                    asm volatile(
                        "mma.sync.aligned.m16n8k16.row.col.f32.f16.f16.f32 "
                        "{%0,%1,%2,%3}, {%4,%5,%6,%7}, {%8,%9}, {%0,%1,%2,%3};\n"
                        : "+f"(c[mi][ni][0]), "+f"(c[mi][ni][1]),
                          "+f"(c[mi][ni][2]), "+f"(c[mi][ni][3])
                        : "r"(af[mi][0]), "r"(af[mi][1]),
                          "r"(af[mi][2]), "r"(af[mi][3]),
                          "r"(bf[ni][0]), "r"(bf[ni][1]));
                }
            }
        }
    }

    // epilogue
    float* Cf = (float*)Cout;
    __half* Ch = (__half*)Cout;
#pragma unroll
    for (int mi = 0; mi < 4; mi++) {
#pragma unroll
        for (int ni = 0; ni < 4; ni++) {
            const int col = colBase + ni * 8 + 2 * rid;
            const float bv0 = __ldg(&bias[col]);
            const float bv1 = __ldg(&bias[col + 1]);
            const int rr0 = row0 + rowBase + mi * 16 + qid;
            if (rr0 < n) {
                float v0 = c[mi][ni][0] + bv0;
                float v1 = c[mi][ni][1] + bv1;
                if (doRelu) { v0 = fmaxf(v0, 0.f); v1 = fmaxf(v1, 0.f); }
                if (outHalf) {
                    *(__half2*)&Ch[(size_t)rr0 * DD + col] = __floats2half2_rn(v0, v1);
                } else {
                    *(float2*)&Cf[(size_t)rr0 * DD + col] = make_float2(v0, v1);
                }
            }
            const int rr1 = rr0 + 8;
            if (rr1 < n) {
                float v2 = c[mi][ni][2] + bv0;
                float v3 = c[mi][ni][3] + bv1;
                if (doRelu) { v2 = fmaxf(v2, 0.f); v3 = fmaxf(v3, 0.f); }
                if (outHalf) {
                    *(__half2*)&Ch[(size_t)rr1 * DD + col] = __floats2half2_rn(v2, v3);
                } else {
                    *(float2*)&Cf[(size_t)rr1 * DD + col] = make_float2(v2, v3);
                }
            }
        }
    }
}

// ---------------- launch ----------------
extern "C" void kernel_launch(void* const* d_in, const int* in_sizes, int n_in,
                              void* d_out, int out_size) {
    const float* x   = (const float*)d_in[0];
    const void*  ei  = d_in[1];
    const float* W1l = (const float*)d_in[2];
    const float* b1  = (const float*)d_in[3];
    const float* W1r = (const float*)d_in[4];
    const float* W2l = (const float*)d_in[5];
    const float* b2  = (const float*)d_in[6];
    const float* W2r = (const float*)d_in[7];
    float* out = (float*)d_out;

    void* p;
    cudaGetSymbolAddress(&p, g_xh);  __half* xh  = (__half*)p;
    cudaGetSymbolAddress(&p, g_agg); __half* agg = (__half*)p;
    cudaGetSymbolAddress(&p, g_h);   __half* h   = (__half*)p;
    cudaGetSymbolAddress(&p, g_wl1); __half* wl1 = (__half*)p;
    cudaGetSymbolAddress(&p, g_wr1); __half* wr1 = (__half*)p;
    cudaGetSymbolAddress(&p, g_wl2); __half* wl2 = (__half*)p;
    cudaGetSymbolAddress(&p, g_wr2); __half* wr2 = (__half*)p;

    cudaFuncSetAttribute(k_gemm, cudaFuncAttributeMaxDynamicSharedMemorySize, SMEM_BYTES);

    const int ngb = (NN + BM - 1) / BM;

    k_detect<<<1, 32>>>((const int*)ei);                        // #0
    k_csr<<<NB, 1024>>>(ei, x, W1l, W1r, W2l, W2r);             // #1

    // Layer 1                                                   // #2, #3 (ncu window on #3)
    k_agg<<<(NN + 7) / 8, 256>>>(xh, agg);
    k_gemm<<<ngb, NTHR, SMEM_BYTES>>>(agg, xh, wl1, wr1, b1, h, NN, 1, 1);

    // Layer 2                                                   // #4, #5
    k_agg<<<(NN + 7) / 8, 256>>>(h, agg);
    k_gemm<<<ngb, NTHR, SMEM_BYTES>>>(agg, h, wl2, wr2, b2, out, NN, 0, 0);
}

// round 15
// speedup vs baseline: 3.6090x; 1.0014x over previous
#include <cuda_runtime.h>
#include <cuda_fp16.h>
#include <cstdint>

#define NN 100000
#define NE 625000
#define DD 128
#define NB 98   // ceil(NN/1024) — persistent CSR grid

// GEMM tiling: block 128x128, 8 warps (2x4), warp tile 64x32, fp16 m16n8k16, 2 CTAs/SM
#define BM 128
#define BN 128
#define BK 32
#define NTHR 256
#define PITCH 40                                   // halfs per row (32 data + 8 pad)
#define STAGE_HALFS ((BM + BN) * PITCH)            // 10240
#define SMEM_BYTES (3 * STAGE_HALFS * 2)           // 3 stages = 61440 B

// ---------------- device scratch (static, allowed) ----------------
__device__ int    g_is64;
__device__ int    g_bar_arrive;
__device__ int    g_bar_gen;
__device__ int    g_deg[NN];
__device__ int    g_off[NN];
__device__ int    g_cur[NN];
__device__ int    g_bsum[NB];
__device__ int    g_csr[NE];
__device__ __half g_xh[(size_t)NN * DD];    // fp16 copy of x
__device__ __half g_agg[(size_t)NN * DD];   // fp16 aggregate
__device__ __half g_h[(size_t)NN * DD];     // fp16 hidden
__device__ __half g_wl1[DD * DD];           // fp16 weights
__device__ __half g_wr1[DD * DD];
__device__ __half g_wl2[DD * DD];
__device__ __half g_wr2[DD * DD];

// ---------------- helpers ----------------
__device__ __forceinline__ uint32_t smem_u32(const void* p) {
    uint32_t a;
    asm("{ .reg .u64 t; cvta.to.shared.u64 t, %1; cvt.u32.u64 %0, t; }" : "=r"(a) : "l"(p));
    return a;
}
__device__ __forceinline__ void cp16(uint32_t dst, const void* src, int sz) {
    asm volatile("cp.async.cg.shared.global [%0], [%1], 16, %2;"
                 :: "r"(dst), "l"(src), "r"(sz) : "memory");
}
__device__ __forceinline__ void cp_commit() {
    asm volatile("cp.async.commit_group;" ::: "memory");
}
__device__ __forceinline__ void cp_wait1() {
    asm volatile("cp.async.wait_group 1;" ::: "memory");
}
__device__ __forceinline__ void ldsm4(unsigned& r0, unsigned& r1, unsigned& r2,
                                      unsigned& r3, uint32_t addr) {
    asm volatile("ldmatrix.sync.aligned.m8n8.x4.shared.b16 {%0,%1,%2,%3}, [%4];"
                 : "=r"(r0), "=r"(r1), "=r"(r2), "=r"(r3) : "r"(addr));
}

// ---------------- dtype detection + barrier reset ----------------
__global__ void k_detect(const int* __restrict__ w) {
    int lane = threadIdx.x;
    int nz = 0;
    if (w[2 * lane + 1] != 0) nz = 1;
    if (w[2 * (lane + 32) + 1] != 0) nz = 1;
    unsigned m = __ballot_sync(0xFFFFFFFF, nz);
    if (lane == 0) {
        g_is64 = (m == 0u) ? 1 : 0;
        g_bar_arrive = 0;
        g_bar_gen = 0;
    }
}

__device__ __forceinline__ int edge_at(const void* ei, int idx, int is64) {
    if (is64) return (int)((const long long*)ei)[idx];
    return ((const int*)ei)[idx];
}

// ---------------- wide x -> fp16 conversion (one float4 per thread) ----------------
__global__ void k_cvt(const float* __restrict__ x) {
    int i = blockIdx.x * blockDim.x + threadIdx.x;
    if (i < NN * DD / 4) {
        float4 v = ((const float4*)x)[i];
        __half2* xh = (__half2*)g_xh;
        xh[2 * i]     = __floats2half2_rn(v.x, v.y);
        xh[2 * i + 1] = __floats2half2_rn(v.z, v.w);
    }
}

// ---------------- software grid barrier ----------------
__device__ __forceinline__ void gridbar(int* gen) {
    __threadfence();
    __syncthreads();
    if (threadIdx.x == 0) {
        int my = *gen + 1;
        if (atomicAdd(&g_bar_arrive, 1) == NB - 1) {
            atomicExch(&g_bar_arrive, 0);
            __threadfence();
            atomicExch(&g_bar_gen, my);
        } else {
            while (atomicAdd(&g_bar_gen, 0) != my) { }
        }
        *gen = my;
    }
    __syncthreads();
}

// ---------------- fused CSR build + weight fp16 conversion ----------------
__global__ __launch_bounds__(1024)
void k_csr(const void* __restrict__ ei,
           const float* __restrict__ W1l, const float* __restrict__ W1r,
           const float* __restrict__ W2l, const float* __restrict__ W2r) {
    __shared__ int s[1024];
    const int tid = threadIdx.x;
    const int bid = blockIdx.x;
    const int gid = bid * 1024 + tid;
    const int is64 = g_is64;
    int gen = 0;

    if (gid < NN) { g_deg[gid] = 0; g_cur[gid] = 0; }
    if (gid < DD * DD) {
        g_wl1[gid] = __float2half_rn(W1l[gid]);
        g_wr1[gid] = __float2half_rn(W1r[gid]);
        g_wl2[gid] = __float2half_rn(W2l[gid]);
        g_wr2[gid] = __float2half_rn(W2r[gid]);
    }
    gridbar(&gen);

    for (int e = gid; e < NE; e += NB * 1024)
        atomicAdd(&g_deg[edge_at(ei, NE + e, is64)], 1);
    gridbar(&gen);

    {
        int v = (gid < NN) ? g_deg[gid] : 0;
        s[tid] = v;
        __syncthreads();
        for (int o = 1; o < 1024; o <<= 1) {
            int t = (tid >= o) ? s[tid - o] : 0;
            __syncthreads();
            s[tid] += t;
            __syncthreads();
        }
        if (gid < NN) g_off[gid] = s[tid] - v;
        if (tid == 1023) g_bsum[bid] = s[tid];
    }
    gridbar(&gen);

    if (bid == 0) {
        int v = (tid < NB) ? g_bsum[tid] : 0;
        if (tid < 128) s[tid] = v;
        __syncthreads();
        for (int o = 1; o < 128; o <<= 1) {
            int t = (tid >= o && tid < 128) ? s[tid - o] : 0;
            __syncthreads();
            if (tid < 128) s[tid] += t;
            __syncthreads();
        }
        if (tid < NB) g_bsum[tid] = s[tid] - v;
    }
    gridbar(&gen);

    if (gid < NN) g_off[gid] += g_bsum[bid];
    gridbar(&gen);

    for (int e = gid; e < NE; e += NB * 1024) {
        int d = edge_at(ei, NE + e, is64);
        int pos = g_off[d] + atomicAdd(&g_cur[d], 1);
        g_csr[pos] = edge_at(ei, e, is64);
    }
}

// ---------------- mean aggregation: one warp per node, fp16 in/out, fp32 accum ----------------
__global__ void k_agg(const __half* __restrict__ X, __half* __restrict__ out) {
    int warp = (blockIdx.x * blockDim.x + threadIdx.x) >> 5;
    if (warp >= NN) return;
    int lane = threadIdx.x & 31;
    int beg = g_off[warp];
    int d = g_deg[warp];
    const uint2* Xv = (const uint2*)X;   // 4 halfs per lane slot; 32 slots per row
    float4 acc = make_float4(0.f, 0.f, 0.f, 0.f);
    int j = 0;
    for (; j + 1 < d; j += 2) {
        int s0 = __ldg(&g_csr[beg + j]);
        int s1 = __ldg(&g_csr[beg + j + 1]);
        uint2 u0 = __ldg(&Xv[(size_t)s0 * 32 + lane]);
        uint2 u1 = __ldg(&Xv[(size_t)s1 * 32 + lane]);
        float2 a = __half22float2(*(__half2*)&u0.x);
        float2 b = __half22float2(*(__half2*)&u0.y);
        float2 e = __half22float2(*(__half2*)&u1.x);
        float2 f = __half22float2(*(__half2*)&u1.y);
        acc.x += a.x + e.x; acc.y += a.y + e.y;
        acc.z += b.x + f.x; acc.w += b.y + f.y;
    }
    if (j < d) {
        int s0 = __ldg(&g_csr[beg + j]);
        uint2 u0 = __ldg(&Xv[(size_t)s0 * 32 + lane]);
        float2 a = __half22float2(*(__half2*)&u0.x);
        float2 b = __half22float2(*(__half2*)&u0.y);
        acc.x += a.x; acc.y += a.y; acc.z += b.x; acc.w += b.y;
    }
    float inv = (d > 0) ? (1.0f / (float)d) : 0.0f;
    uint2 o;
    *(__half2*)&o.x = __floats2half2_rn(acc.x * inv, acc.y * inv);
    *(__half2*)&o.y = __floats2half2_rn(acc.z * inv, acc.w * inv);
    ((uint2*)out)[(size_t)warp * 32 + lane] = o;
}

// ---------------- fp16 mma.sync fused dual GEMM, ldmatrix, cp.async 3-stage, 2 CTAs/SM ----------------
// C[i][o] = sum_k A1[i][k]*Wl[o][k] + sum_k A2[i][k]*Wr[o][k] + b[o]  (opt ReLU)
// Block 128x128, 8 warps (2x4), warp tile 64x32 = 4x4 m16n8k16 frags, BK=32.
__global__ __launch_bounds__(NTHR, 2)
void k_gemm(const __half* __restrict__ A1, const __half* __restrict__ A2,
            const __half* __restrict__ Wl, const __half* __restrict__ Wr,
            const float* __restrict__ bias, void* __restrict__ Cout,
            int n, int doRelu, int outHalf)
{
    extern __shared__ __half S[];
    const uint32_t sb = smem_u32(S);
    const int tid  = threadIdx.x;
    const int lane = tid & 31;
    const int wid  = tid >> 5;
    const int warpM = wid >> 2;            // 0..1  (64-row slices)
    const int warpN = wid & 3;             // 0..3  (32-col slices)
    const int rowBase = warpM * 64;
    const int colBase = warpN * 32;
    const int row0 = blockIdx.x * BM;
    const int qid = lane >> 2;             // 0..7
    const int rid = lane & 3;              // 0..3

    // ldmatrix lane-address components (halfs)
    const int a_lrow = rowBase + (lane & 7) + ((lane >> 3) & 1) * 8;
    const int a_lcol = (lane >> 4) * 8;
    const int b_lrow = colBase + (lane & 7) + (lane >> 4) * 8;
    const int b_lcol = ((lane >> 3) & 1) * 8;

    float c[4][4][4];
#pragma unroll
    for (int mi = 0; mi < 4; mi++)
#pragma unroll
        for (int ni = 0; ni < 4; ni++)
#pragma unroll
            for (int t = 0; t < 4; t++) c[mi][ni][t] = 0.f;

    // tile loader: tile t (0..7) -> slot t%3. Rows are 32 halfs = 64B = 4x cp16.
    auto load_tile = [&](int t) {
        if (t < 8) {
            const __half* Asrc = (t < 4) ? A1 : A2;
            const __half* Bsrc = (t < 4) ? Wl : Wr;
            const int kc = (t & 3) * BK;
            const uint32_t abase = sb + (uint32_t)(t % 3) * (STAGE_HALFS * 2);
            const uint32_t bbase = abase + BM * PITCH * 2;
#pragma unroll
            for (int i = 0; i < 2; i++) {
                int ch = tid + i * NTHR;                // 0..511 (128 rows x 4)
                int row = ch >> 2, c4 = ch & 3;
                int gr = row0 + row;
                int ok = (gr < n);
                const __half* src = Asrc + (size_t)(ok ? gr : 0) * DD + kc + c4 * 8;
                cp16(abase + row * (PITCH * 2) + c4 * 16, src, ok ? 16 : 0);
            }
#pragma unroll
            for (int i = 0; i < 2; i++) {
                int ch = tid + i * NTHR;                // 0..511 (128 rows x 4)
                int nr = ch >> 2, c4 = ch & 3;
                cp16(bbase + nr * (PITCH * 2) + c4 * 16,
                     Bsrc + (size_t)nr * DD + kc + c4 * 8, 16);
            }
        }
        cp_commit();   // commit even when empty to keep group accounting uniform
    };

    load_tile(0);
    load_tile(1);

    for (int t = 0; t < 8; t++) {
        cp_wait1();          // tile t's group complete (1 group may stay in flight)
        __syncthreads();     // writes visible; prev compute on reused slot done
        load_tile(t + 2);    // slot (t+2)%3 was tile t-1: free now

        const uint32_t slotBase = sb + (uint32_t)(t % 3) * (STAGE_HALFS * 2);
        const uint32_t aAddr = slotBase + (uint32_t)(a_lrow * PITCH + a_lcol) * 2;
        const uint32_t bAddr = slotBase + (uint32_t)(BM * PITCH) * 2
                             + (uint32_t)(b_lrow * PITCH + b_lcol) * 2;

#pragma unroll
        for (int kk = 0; kk < BK; kk += 16) {
            unsigned af[4][4];
            unsigned bf[4][2];
#pragma unroll
            for (int mi = 0; mi < 4; mi++)
                ldsm4(af[mi][0], af[mi][1], af[mi][2], af[mi][3],
                      aAddr + (uint32_t)(mi * 16 * PITCH + kk) * 2);
#pragma unroll
            for (int np = 0; np < 2; np++)
                ldsm4(bf[2 * np][0], bf[2 * np][1], bf[2 * np + 1][0], bf[2 * np + 1][1],
                      bAddr + (uint32_t)(np * 16 * PITCH + kk) * 2);
#pragma unroll
            for (int ni = 0; ni < 4; ni++) {
#pragma unroll
                for (int mi = 0; mi < 4; mi++) {
                    asm volatile(
                        "mma.sync.aligned.m16n8k16.row.col.f32.f16.f16.f32 "
                        "{%0,%1,%2,%3}, {%4,%5,%6,%7}, {%8,%9}, {%0,%1,%2,%3};\n"
                        : "+f"(c[mi][ni][0]), "+f"(c[mi][ni][1]),
                          "+f"(c[mi][ni][2]), "+f"(c[mi][ni][3])
                        : "r"(af[mi][0]), "r"(af[mi][1]),
                          "r"(af[mi][2]), "r"(af[mi][3]),
                          "r"(bf[ni][0]), "r"(bf[ni][1]));
                }
            }
        }
    }

    // epilogue
    float* Cf = (float*)Cout;
    __half* Ch = (__half*)Cout;
#pragma unroll
    for (int mi = 0; mi < 4; mi++) {
#pragma unroll
        for (int ni = 0; ni < 4; ni++) {
            const int col = colBase + ni * 8 + 2 * rid;
            const float bv0 = __ldg(&bias[col]);
            const float bv1 = __ldg(&bias[col + 1]);
            const int rr0 = row0 + rowBase + mi * 16 + qid;
            if (rr0 < n) {
                float v0 = c[mi][ni][0] + bv0;
                float v1 = c[mi][ni][1] + bv1;
                if (doRelu) { v0 = fmaxf(v0, 0.f); v1 = fmaxf(v1, 0.f); }
                if (outHalf) {
                    *(__half2*)&Ch[(size_t)rr0 * DD + col] = __floats2half2_rn(v0, v1);
                } else {
                    *(float2*)&Cf[(size_t)rr0 * DD + col] = make_float2(v0, v1);
                }
            }
            const int rr1 = rr0 + 8;
            if (rr1 < n) {
                float v2 = c[mi][ni][2] + bv0;
                float v3 = c[mi][ni][3] + bv1;
                if (doRelu) { v2 = fmaxf(v2, 0.f); v3 = fmaxf(v3, 0.f); }
                if (outHalf) {
                    *(__half2*)&Ch[(size_t)rr1 * DD + col] = __floats2half2_rn(v2, v3);
                } else {
                    *(float2*)&Cf[(size_t)rr1 * DD + col] = make_float2(v2, v3);
                }
            }
        }
    }
}

// ---------------- launch ----------------
extern "C" void kernel_launch(void* const* d_in, const int* in_sizes, int n_in,
                              void* d_out, int out_size) {
    const float* x   = (const float*)d_in[0];
    const void*  ei  = d_in[1];
    const float* W1l = (const float*)d_in[2];
    const float* b1  = (const float*)d_in[3];
    const float* W1r = (const float*)d_in[4];
    const float* W2l = (const float*)d_in[5];
    const float* b2  = (const float*)d_in[6];
    const float* W2r = (const float*)d_in[7];
    float* out = (float*)d_out;

    void* p;
    cudaGetSymbolAddress(&p, g_xh);  __half* xh  = (__half*)p;
    cudaGetSymbolAddress(&p, g_agg); __half* agg = (__half*)p;
    cudaGetSymbolAddress(&p, g_h);   __half* h   = (__half*)p;
    cudaGetSymbolAddress(&p, g_wl1); __half* wl1 = (__half*)p;
    cudaGetSymbolAddress(&p, g_wr1); __half* wr1 = (__half*)p;
    cudaGetSymbolAddress(&p, g_wl2); __half* wl2 = (__half*)p;
    cudaGetSymbolAddress(&p, g_wr2); __half* wr2 = (__half*)p;

    cudaFuncSetAttribute(k_gemm, cudaFuncAttributeMaxDynamicSharedMemorySize, SMEM_BYTES);

    const int ngb = (NN + BM - 1) / BM;

    k_detect<<<1, 32>>>((const int*)ei);                        // #0
    k_cvt<<<(NN * DD / 4 + 255) / 256, 256>>>(x);               // #1 wide x->fp16
    k_csr<<<NB, 1024>>>(ei, W1l, W1r, W2l, W2r);                // #2

    // Layer 1                                                   // #3 (ncu window), #4
    k_agg<<<(NN + 7) / 8, 256>>>(xh, agg);
    k_gemm<<<ngb, NTHR, SMEM_BYTES>>>(agg, xh, wl1, wr1, b1, h, NN, 1, 1);

    // Layer 2                                                   // #5, #6
    k_agg<<<(NN + 7) / 8, 256>>>(h, agg);
    k_gemm<<<ngb, NTHR, SMEM_BYTES>>>(agg, h, wl2, wr2, b2, out, NN, 0, 0);
}